// round 3
// baseline (speedup 1.0000x reference)
#include <cuda_runtime.h>

#define UNITS 64
#define BATCH 64
#define LL 32
#define IDIM 256          // input dim of gate GEMM = C + 3U
#define NZ 448            // gate output cols (192 r + 256 z)
#define NT 64             // n-tile width for phase 1
#define NP1 7             // phase-1 tiles per cell (448/64)
#define NP2 4             // phase-2 tiles per cell (64 b / 16)
#define GRID 148
#define TPB 256
#define QS 68             // padded row stride for q_s [k][b]
#define DIAGS 63
#define TOTAL_ITEMS (11*1024)   // sum over diagonals of 11*n_d
#define SMEM_BYTES (135168)     // 256*68*4 + 256*64*4

// ---------------- global scratch (allowed: __device__ arrays) ----------------
__device__ float g_states [33*33*BATCH*UNITS];  // h at [i][j][b][u]
__device__ float g_statesT[33*33*BATCH*UNITS];  // h at [i][j][u][b]
__device__ float g_xT[1024*64*64];              // inputs transposed: [t][c][b]
__device__ float g_RZ[32*NZ*BATCH];             // per-row-slot scratch [i][n][b]
__device__ int   g_p1done[1024];
__device__ int   g_hdone [1024];

// ---------------- sync helpers ----------------
__device__ __forceinline__ int ld_acq(const int* p) {
    int v;
    asm volatile("ld.global.acquire.gpu.b32 %0, [%1];" : "=r"(v) : "l"(p) : "memory");
    return v;
}
__device__ __forceinline__ void spin_ge(const int* p, int v) {
    while (ld_acq(p) < v) { __nanosleep(40); }
}

// ---------------- init: zero states/counters + transpose inputs ----------------
__global__ void init_kernel(const float* __restrict__ in) {
    int tid = blockIdx.x * blockDim.x + threadIdx.x;
    int stride = gridDim.x * blockDim.x;
    const int NS = 33*33*BATCH*UNITS;
    for (int idx = tid; idx < NS; idx += stride) {
        g_states[idx] = 0.f;
        g_statesT[idx] = 0.f;
    }
    for (int idx = tid; idx < 2048; idx += stride) {
        if (idx < 1024) g_p1done[idx] = 0; else g_hdone[idx - 1024] = 0;
    }
    const int NX = 1024*64*64;
    for (int idx = tid; idx < NX; idx += stride) {
        int b = idx & 63;
        int c = (idx >> 6) & 63;
        int t = idx >> 12;
        // in[b][c][i][j], (i,j) flattened row-major == t
        g_xT[idx] = in[(b*64 + c)*1024 + t];
    }
}

// ---------------- main persistent dataflow kernel ----------------
__global__ __launch_bounds__(TPB, 1)
void gru_kernel(const float* __restrict__ W, const float* __restrict__ U_rec,
                const float* __restrict__ bias, const float* __restrict__ W_ij,
                float* __restrict__ out)
{
    extern __shared__ float sm[];
    const int tid = threadIdx.x;

    for (int item = blockIdx.x; item < TOTAL_ITEMS; item += gridDim.x) {
        // ---- decode item -> (diagonal d, phase, cell, tile) ----
        int d = 0, base = 0, nd = 1, i0 = 0;
        for (d = 0; d < DIAGS; d++) {
            i0 = (d > 31) ? (d - 31) : 0;
            int i1 = (d < 31) ? d : 31;
            nd = i1 - i0 + 1;
            int sz = 11 * nd;
            if (item < base + sz) break;
            base += sz;
        }
        int local = item - base;

        if (local < NP1 * nd) {
            // ================= PHASE 1: gate GEMM tile (64b x 64n x 256k) =================
            int ci = local / NP1, nt = local % NP1;
            int i = i0 + ci, j = d - i;

            if (tid == 0) {
                if (i > 0 && j > 0) spin_ge(&g_hdone[(i-1)*32 + (j-1)], NP2);
                if (i > 0)          spin_ge(&g_hdone[(i-1)*32 + j    ], NP2);
                if (j > 0)          spin_ge(&g_hdone[ i   *32 + (j-1)], NP2);
            }
            __syncthreads();

            float* q_s = sm;              // [256][QS], layout [k][b]
            float* W_s = sm + 256*QS;     // [256][64], layout [k][n]

            // q = [h_top, h_left, h_diag, s_ij] ; borders of statesT are zero so no bounds logic
            const float* src0 = &g_statesT[((size_t)( i   *33 + (j+1)))*4096];  // h_top  = h(i-1,j)
            const float* src1 = &g_statesT[((size_t)((i+1)*33 +  j   ))*4096];  // h_left = h(i,j-1)
            const float* src2 = &g_statesT[((size_t)( i   *33 +  j   ))*4096];  // h_diag = h(i-1,j-1)
            const float* src3 = &g_xT[(size_t)(i*32 + j)*4096];                 // s_ij (layout [c][b])
            const float* srcs[4] = {src0, src1, src2, src3};
            #pragma unroll
            for (int p = 0; p < 4; p++) {
                const float4* sp = (const float4*)srcs[p];
                for (int e = tid; e < 1024; e += TPB) {
                    int u = e >> 4, b4 = (e & 15) << 2;
                    *(float4*)&q_s[(p*64 + u)*QS + b4] = sp[e];
                }
            }
            {   // W tile: columns [nt*64, nt*64+64)
                const float4* wp = (const float4*)(W + nt*NT);   // row stride = 448 fl = 112 f4
                for (int e = tid; e < 4096; e += TPB) {
                    int k = e >> 4, n4 = e & 15;
                    *(float4*)&W_s[(k << 6) + (n4 << 2)] = wp[k*112 + n4];
                }
            }
            __syncthreads();

            const int tx = tid & 15, ty = tid >> 4;   // tx: n-group(4n), ty: b-group(4b)
            float4 a0 = {0.f,0.f,0.f,0.f}, a1 = a0, a2 = a0, a3 = a0;  // [n][b-vec]
            const float* qp  = q_s + (ty << 2);
            const float* wpS = W_s + (tx << 2);
            #pragma unroll 4
            for (int k = 0; k < 256; k++) {
                float4 qv = *(const float4*)(qp  + k*QS);
                float4 wv = *(const float4*)(wpS + (k << 6));
                a0.x += qv.x*wv.x; a0.y += qv.y*wv.x; a0.z += qv.z*wv.x; a0.w += qv.w*wv.x;
                a1.x += qv.x*wv.y; a1.y += qv.y*wv.y; a1.z += qv.z*wv.y; a1.w += qv.w*wv.y;
                a2.x += qv.x*wv.z; a2.y += qv.y*wv.z; a2.z += qv.z*wv.z; a2.w += qv.w*wv.z;
                a3.x += qv.x*wv.w; a3.y += qv.y*wv.w; a3.z += qv.z*wv.w; a3.w += qv.w*wv.w;
            }
            int n0 = nt*NT + (tx << 2);
            float b0 = bias[n0+0], b1c = bias[n0+1], b2c = bias[n0+2], b3c = bias[n0+3];
            a0.x += b0;  a0.y += b0;  a0.z += b0;  a0.w += b0;
            a1.x += b1c; a1.y += b1c; a1.z += b1c; a1.w += b1c;
            a2.x += b2c; a2.y += b2c; a2.z += b2c; a2.w += b2c;
            a3.x += b3c; a3.y += b3c; a3.z += b3c; a3.w += b3c;

            float* rz = &g_RZ[(size_t)i * NZ * 64];
            int bb = ty << 2;
            *(float4*)&rz[(n0+0)*64 + bb] = a0;
            *(float4*)&rz[(n0+1)*64 + bb] = a1;
            *(float4*)&rz[(n0+2)*64 + bb] = a2;
            *(float4*)&rz[(n0+3)*64 + bb] = a3;

            __threadfence();
            __syncthreads();
            if (tid == 0) atomicAdd(&g_p1done[i*32 + j], 1);
        } else {
            // ================= PHASE 2: update GEMM + gates (16b x 64u x 256k) =================
            int l2 = local - NP1*nd;
            int ci = l2 / NP2, bt = l2 % NP2;
            int i = i0 + ci, j = d - i;

            if (tid == 0) spin_ge(&g_p1done[i*32 + j], NP1);
            __syncthreads();

            float* U_s = sm;                // [256][64]: rows 0..191 U_rec, 192..255 W_ij
            float* m_s = sm + 256*64;       // [256][16]: gated recurrent input (+ s part)
            float* h_s = m_s + 256*16;      // [16][65]

            {
                const float4* up  = (const float4*)U_rec;   // 3072 f4
                const float4* wij = (const float4*)W_ij;    // 1024 f4
                for (int e = tid; e < 4096; e += TPB) {
                    float4 v = (e < 3072) ? up[e] : wij[e - 3072];
                    *(float4*)&U_s[e << 2] = v;
                }
            }
            const float* rz  = &g_RZ[(size_t)i * NZ * 64];
            const float* hlT = &g_statesT[((size_t)((i+1)*33 +  j   ))*4096];
            const float* htT = &g_statesT[((size_t)( i   *33 + (j+1)))*4096];
            const float* hdT = &g_statesT[((size_t)( i   *33 +  j   ))*4096];
            const float* xs  = &g_xT[(size_t)(i*32 + j)*4096];

            // m = r * [h_left, h_top, h_diag]  (rows 0..191), s_ij (rows 192..255)
            for (int e = tid; e < 4096; e += TPB) {
                int k = e >> 4, b = e & 15;
                int ba = (bt << 4) + b;
                float v;
                if (k < 192) {
                    int g = k >> 6, kk = k & 63;
                    const float* hT = (g == 0) ? hlT : (g == 1) ? htT : hdT;
                    float h = hT[(kk << 6) + ba];
                    float r = rz[(k << 6) + ba];
                    r = 1.f / (1.f + __expf(-r));
                    v = r * h;
                } else {
                    v = xs[((k - 192) << 6) + ba];
                }
                m_s[(k << 4) + b] = v;
            }
            __syncthreads();

            const int u = tid & 63, bsub = tid >> 6;  // 4 consecutive b per thread
            float bj = bias[448 + u];
            float4 acc = {bj, bj, bj, bj};
            const float* mp = m_s + (bsub << 2);
            #pragma unroll 4
            for (int k = 0; k < 256; k++) {
                float  un = U_s[(k << 6) + u];
                float4 mv = *(const float4*)(mp + (k << 4));
                acc.x += mv.x*un; acc.y += mv.y*un; acc.z += mv.z*un; acc.w += mv.w*un;
            }

            const float* hl = &g_states[((size_t)((i+1)*33 +  j   ))*4096];
            const float* ht = &g_states[((size_t)( i   *33 + (j+1)))*4096];
            const float* hd = &g_states[((size_t)( i   *33 +  j   ))*4096];
            float* hout  = &g_states [((size_t)((i+1)*33 + (j+1)))*4096];
            const float* zb = rz + 192*64;
            float accs[4] = {acc.x, acc.y, acc.z, acc.w};
            bool last = (i == 31) && (j == 31);
            #pragma unroll
            for (int q = 0; q < 4; q++) {
                int bl = (bsub << 2) + q;
                int ba = (bt << 4) + bl;
                float z0 = zb[( u        << 6) + ba];   // zi
                float z1 = zb[((64 + u)  << 6) + ba];   // zl
                float z2 = zb[((128 + u) << 6) + ba];   // zt
                float z3 = zb[((192 + u) << 6) + ba];   // zd
                float mx = fmaxf(fmaxf(z0, z1), fmaxf(z2, z3));
                float e0 = __expf(z0 - mx), e1 = __expf(z1 - mx);
                float e2 = __expf(z2 - mx), e3 = __expf(z3 - mx);
                float inv = 1.f / (e0 + e1 + e2 + e3);
                float hh = tanhf(accs[q]);
                float vl = hl[(ba << 6) + u];
                float vt = ht[(ba << 6) + u];
                float vd = hd[(ba << 6) + u];
                float h  = (e1*vl + e2*vt + e3*vd + e0*hh) * inv;
                hout[(ba << 6) + u] = h;
                h_s[bl*65 + u] = h;
                if (last) out[(ba << 6) + u] = h;
            }
            __syncthreads();
            float* houtT = &g_statesT[((size_t)((i+1)*33 + (j+1)))*4096];
            for (int e = tid; e < 1024; e += TPB) {
                int b = e & 15, uu = e >> 4;
                houtT[(uu << 6) + (bt << 4) + b] = h_s[b*65 + uu];
            }
            __threadfence();
            __syncthreads();
            if (tid == 0) atomicAdd(&g_hdone[i*32 + j], 1);
        }
    }
}

extern "C" void kernel_launch(void* const* d_in, const int* in_sizes, int n_in,
                              void* d_out, int out_size) {
    const float* inputs = (const float*)d_in[0];
    const float* W      = (const float*)d_in[1];
    const float* U_rec  = (const float*)d_in[2];
    const float* bias   = (const float*)d_in[3];
    const float* W_ij   = (const float*)d_in[4];
    float* out = (float*)d_out;

    cudaFuncSetAttribute(gru_kernel, cudaFuncAttributeMaxDynamicSharedMemorySize, SMEM_BYTES);

    init_kernel<<<512, 256>>>(inputs);
    gru_kernel<<<GRID, TPB, SMEM_BYTES>>>(W, U_rec, bias, W_ij, out);
}